// round 17
// baseline (speedup 1.0000x reference)
#include <cuda_runtime.h>
#include <cuda_fp16.h>
#include <math.h>
#include <stdint.h>

// ---------------------------------------------------------------------------
// Actor_Soft_Attention: B=65536, IN=128, HID=256, OUT=8
// mma.sync m16n8k16 fp16/fp32. BM=64 rows/CTA, 112KB smem -> 2 CTAs/SM.
// R17: intra-stage software pipeline — each 32KB weight stage split into two
// 16KB halves (L1: row halves = Wa/Wb; L3: column halves = kb 0..3 / 4..7),
// depth-2 cp.async pipeline so fetches fly under the previous half's compute.
//  L1 (h 0..15): per c0: W2 stage -> att, W1 stage -> h_i tiles. 4Mx2N warps.
//  L3+L4 (h 16..35): x[64x256] over K=640, 2Mx4N warps; fused register L4.
// ---------------------------------------------------------------------------

#define TILE   16384                   // 64 rows x 256B  (A-tile bytes)
#define WBLOB  32768                   // weight stage blob bytes
#define NCTA   1024

#define SM_A   0                       // 5 tiles: h0,h1,s0,s1,s2 (80KB)
#define SM_W   (5 * TILE)              // 81920: one 32KB stage buffer
#define SMEM_BYTES (SM_W + 32768)      // 114688 -> 2 CTAs/SM

// 18 stage blobs: 8 L1 ([64ch x Klo | 64ch x Khi]) + 10 L3 ([128n x 128K])
__device__ __align__(16) __half g_wstage[18 * 16384];

// swizzled byte offset: row-major 256B rows, XOR chunk by (r&7)
__host__ __device__ __forceinline__ uint32_t swz(int r, int ch) {
    return (uint32_t)(r * 256 + ((((ch >> 3) ^ (r & 7)) << 4)) + (ch & 7) * 2);
}

// ---------------- warp primitives ----------------
__device__ __forceinline__ uint32_t smem_u32(const void* p) {
    uint32_t a;
    asm("{ .reg .u64 t; cvta.to.shared.u64 t, %1; cvt.u32.u64 %0, t; }" : "=r"(a) : "l"(p));
    return a;
}
__device__ __forceinline__ void ldsm4(uint32_t* r, uint32_t a) {
    asm volatile("ldmatrix.sync.aligned.m8n8.x4.shared.b16 {%0,%1,%2,%3}, [%4];"
        : "=r"(r[0]), "=r"(r[1]), "=r"(r[2]), "=r"(r[3]) : "r"(a));
}
__device__ __forceinline__ void mma16816(float (&c)[4], const uint32_t a[4],
                                         uint32_t b0, uint32_t b1) {
    asm volatile("mma.sync.aligned.m16n8k16.row.col.f32.f16.f16.f32 "
        "{%0,%1,%2,%3}, {%4,%5,%6,%7}, {%8,%9}, {%0,%1,%2,%3};"
        : "+f"(c[0]), "+f"(c[1]), "+f"(c[2]), "+f"(c[3])
        : "r"(a[0]), "r"(a[1]), "r"(a[2]), "r"(a[3]), "r"(b0), "r"(b1));
}
__device__ __forceinline__ uint32_t packh2(float x, float y) {
    __half2 h = __floats2half2_rn(x, y);
    return *(uint32_t*)&h;
}
__device__ __forceinline__ void cp16(uint32_t dst, const char* src) {
    asm volatile("cp.async.cg.shared.global [%0], [%1], 16;" :: "r"(dst), "l"(src));
}
#define CP_COMMIT() asm volatile("cp.async.commit_group;" ::: "memory")
#define CP_WAIT1()  asm volatile("cp.async.wait_group 1;" ::: "memory")
#define CP_WAIT0()  asm volatile("cp.async.wait_group 0;" ::: "memory")

// fetch one 16KB half (hh = global half index 0..35), one commit group
__device__ __forceinline__ void fetch_half(uint32_t sbW, int hh, int t) {
    if (hh < 16) {
        // L1 stage (hh>>1): contiguous row-half (lo: rows 0..63, hi: 64..127)
        const char* src = (const char*)g_wstage + (size_t)(hh >> 1) * WBLOB
                        + (size_t)(hh & 1) * 16384;
        uint32_t dst = sbW + (uint32_t)((hh & 1) * 16384);
        #pragma unroll
        for (int i = 0; i < 4; i++)
            cp16(dst + (uint32_t)((t + 256 * i) * 16), src + (t + 256 * i) * 16);
    } else {
        // L3 stage: column half (lo: bytes 0..127 of all rows, hi: 128..255)
        int hu = hh - 16;
        const char* src = (const char*)g_wstage + (size_t)(8 + (hu >> 1)) * WBLOB;
        uint32_t coff = (uint32_t)((hu & 1) * 128);
        #pragma unroll
        for (int i = 0; i < 4; i++) {
            int idx = t + 256 * i;
            uint32_t ro = (uint32_t)(idx >> 3) * 256 + (uint32_t)(idx & 7) * 16 + coff;
            cp16(sbW + ro, src + ro);
        }
    }
    CP_COMMIT();
}

// ---- L1: C[16 x 32] += A(16r,K128) * W(32n,K128)^T ----
__device__ __forceinline__ void wgemmL1_one(float (&acc)[4][4],
    uint32_t aBase, int ax, int aHi, uint32_t bBase, int bx, int bHi)
{
    #pragma unroll
    for (int kb = 0; kb < 8; kb++) {
        uint32_t ka  = (uint32_t)(((((kb << 1) | aHi) ^ ax) << 4));
        uint32_t kbb = (uint32_t)(((((kb << 1) | bHi) ^ bx) << 4));
        uint32_t af[4], bf[2][4];
        ldsm4(af, aBase + ka);
        ldsm4(bf[0], bBase + kbb);
        ldsm4(bf[1], bBase + 4096 + kbb);
        #pragma unroll
        for (int j = 0; j < 4; j++)
            mma16816(acc[j], af, bf[j >> 1][(j & 1) * 2], bf[j >> 1][(j & 1) * 2 + 1]);
    }
}
// two A tiles sharing one 32-n-row W tile
__device__ __forceinline__ void wgemmL1_two(float (&c1)[4][4], float (&c2)[4][4],
    uint32_t a1, uint32_t a2, int ax, int aHi, uint32_t bBase, int bx, int bHi)
{
    #pragma unroll
    for (int kb = 0; kb < 8; kb++) {
        uint32_t ka  = (uint32_t)(((((kb << 1) | aHi) ^ ax) << 4));
        uint32_t kbb = (uint32_t)(((((kb << 1) | bHi) ^ bx) << 4));
        uint32_t f1[4], f2[4], bf[2][4];
        ldsm4(f1, a1 + ka);
        ldsm4(f2, a2 + ka);
        ldsm4(bf[0], bBase + kbb);
        ldsm4(bf[1], bBase + 4096 + kbb);
        #pragma unroll
        for (int j = 0; j < 4; j++) {
            uint32_t b0 = bf[j >> 1][(j & 1) * 2], b1 = bf[j >> 1][(j & 1) * 2 + 1];
            mma16816(c1[j], f1, b0, b1);
            mma16816(c2[j], f2, b0, b1);
        }
    }
}
// ---- L3: C[32 x 32] += A(32r,K=64 chunk) * W(32n,K=64 chunk)^T, kb0..kb0+3 ----
__device__ __forceinline__ void wgemm_l3r(float (&acc)[2][4][4],
    uint32_t aBase, int ax, int aHi, uint32_t bBase, int bx, int bHi, int kb0)
{
    #pragma unroll
    for (int k = 0; k < 4; k++) {
        int kb = kb0 + k;
        uint32_t ka  = (uint32_t)(((((kb << 1) | aHi) ^ ax) << 4));
        uint32_t kbb = (uint32_t)(((((kb << 1) | bHi) ^ bx) << 4));
        uint32_t af[2][4], bf[2][4];
        ldsm4(af[0], aBase + ka);
        ldsm4(af[1], aBase + 4096 + ka);
        ldsm4(bf[0], bBase + kbb);
        ldsm4(bf[1], bBase + 4096 + kbb);
        #pragma unroll
        for (int i = 0; i < 2; i++)
            #pragma unroll
            for (int j = 0; j < 4; j++)
                mma16816(acc[i][j], af[i], bf[j >> 1][(j & 1) * 2], bf[j >> 1][(j & 1) * 2 + 1]);
    }
}

// ---------------- weight pre-conversion (18 blobs) ----------------
__global__ void convert_weights(const float* __restrict__ W1, const float* __restrict__ W2,
                                const float* __restrict__ W3)
{
    const int s = blockIdx.x, t = threadIdx.x;
    char* dst = (char*)g_wstage + (size_t)s * WBLOB;
    for (int i = t; i < 4096; i += 256) {
        int r = i >> 5, kq = (i & 31) * 4;
        float4 v;
        if (s < 8) {
            int c0 = s >> 1;
            const float* src = (s & 1) ? W1 : W2;
            int wr = c0 * 64 + (r & 63);
            int wk = ((r >> 6) << 7) + kq;
            v = *(const float4*)(src + (size_t)wr * 256 + wk);
        } else {
            int u = s - 8, nh = u / 5, kc = u % 5;
            v = *(const float4*)(W3 + (size_t)(nh * 128 + r) * 640 + kc * 128 + kq);
        }
        char* d = dst + swz(r, kq);
        *(__half2*)d       = __floats2half2_rn(v.x, v.y);
        *(__half2*)(d + 4) = __floats2half2_rn(v.z, v.w);
    }
}

// ---------------- main kernel ----------------
__global__ __launch_bounds__(256, 2)
void actor_main(const float* __restrict__ state,
                const float* __restrict__ b1, const float* __restrict__ b2,
                const float* __restrict__ b3, const float* __restrict__ W4,
                const float* __restrict__ b4, float* __restrict__ out)
{
    extern __shared__ char smem[];
    const uint32_t sb = smem_u32(smem);
    const uint32_t sbW = sb + SM_W;
    const int t = threadIdx.x, wid = t >> 5, l = t & 31;
    const int wm = wid & 3, wn = wid >> 2;     // L1: 4M x 2N (16r x 32ch)
    const int wm2 = wid & 1, wn4 = wid >> 1;   // L3: 2M x 4N (32r x 32ch)
    const int g = l >> 2, tq = l & 3;
    const int cta = blockIdx.x;

    const int aRow = l & 15, aHi = l >> 4, ax = l & 7;
    const int bRow = (l & 7) + ((l >> 4) & 1) * 8, bHi = (l >> 3) & 1, bx = l & 7;

    // ---- W4 register B-fragments: k = nh*128 + wn4*32 + kb*16 ----
    uint32_t w4f[2][2][2];
    {
        const int o = l >> 2, r2 = (l & 3) * 2;
        #pragma unroll
        for (int nh = 0; nh < 2; nh++)
            #pragma unroll
            for (int kb = 0; kb < 2; kb++) {
                int kbase = nh * 128 + wn4 * 32 + kb * 16;
                float2 v0 = *(const float2*)&W4[(size_t)o * 256 + kbase + r2];
                float2 v1 = *(const float2*)&W4[(size_t)o * 256 + kbase + r2 + 8];
                w4f[nh][kb][0] = packh2(v0.x, v0.y);
                w4f[nh][kb][1] = packh2(v1.x, v1.y);
            }
    }

    // ---- prologue: pipeline warmup (halves 0,1), then state staging ----
    fetch_half(sbW, 0, t);
    fetch_half(sbW, 1, t);
    {
        const float4* gs = (const float4*)(state + (size_t)cta * 64 * 384);
        for (int i4 = t; i4 < 6144; i4 += 256) {
            int r = i4 / 96, cq = (i4 % 96) * 4;
            float4 v = gs[i4];
            char* d = smem + SM_A + (2 + (cq >> 7)) * TILE + swz(r, cq & 127);
            *(__half2*)d       = __floats2half2_rn(v.x, v.y);
            *(__half2*)(d + 4) = __floats2half2_rn(v.z, v.w);
        }
    }

    const uint32_t aS0 = sb + SM_A + 2 * TILE + (uint32_t)((wm * 16 + aRow) * 256);
    const uint32_t aS1 = aS0 + TILE, aS2 = aS0 + 2 * TILE;
    const uint32_t bWa = sbW + (uint32_t)((wn * 32 + bRow) * 256);
    const uint32_t bWb = bWa + 64 * 256;
    const uint32_t aL3 = sb + SM_A + (uint32_t)((wm2 * 32 + aRow) * 256);
    const uint32_t bL3 = sbW + (uint32_t)((wn4 * 32 + bRow) * 256);

    float att[4][4];
    float p0[4][4], p1[4][4], p2[4][4];
    float oat[2][4] = {};
    float xacc[2][4][4];

    // =====================================================================
    // 36-half pipelined main loop
    // =====================================================================
    for (int h = 0; h < 36; h++) {
        if (h == 15 || h == 35) { CP_WAIT0(); } else { CP_WAIT1(); }
        __syncthreads();

        if (h < 16) {
            const int s = h >> 1, c0 = s >> 1;
            if (!(h & 1)) {
                // lo half: Wa rows — s0 pass
                #pragma unroll
                for (int j = 0; j < 4; j++)
                    #pragma unroll
                    for (int e = 0; e < 4; e++) { p0[j][e] = 0.f; p1[j][e] = 0.f; p2[j][e] = 0.f; }
                wgemmL1_one(p0, aS0, ax, aHi, bWa, bx, bHi);
            } else {
                // hi half: Wb rows — neighbor passes + epilogue
                wgemmL1_two(p1, p2, aS1, aS2, ax, aHi, bWb, bx, bHi);
                if (!(s & 1)) {
                    // W2 stage -> attention coefficient
                    #pragma unroll
                    for (int j = 0; j < 4; j++) {
                        int colg = c0 * 64 + wn * 32 + j * 8 + 2 * tq;
                        float bb0 = __ldg(&b2[colg]), bb1 = __ldg(&b2[colg + 1]);
                        #pragma unroll
                        for (int e = 0; e < 4; e++) {
                            float bb = (e & 1) ? bb1 : bb0;
                            float e0 = fmaxf(p0[j][e] + p1[j][e] + bb, 0.0f);
                            float e1 = fmaxf(p0[j][e] + p2[j][e] + bb, 0.0f);
                            att[j][e] = __fdividef(1.0f, 1.0f + __expf(e1 - e0));
                        }
                    }
                } else {
                    // W1 stage -> h_i into tiles 0/1
                    #pragma unroll
                    for (int j = 0; j < 4; j++) {
                        int colg = c0 * 64 + wn * 32 + j * 8 + 2 * tq;
                        float bb0 = __ldg(&b1[colg]), bb1 = __ldg(&b1[colg + 1]);
                        #pragma unroll
                        for (int eh = 0; eh < 2; eh++) {
                            float hv[2];
                            #pragma unroll
                            for (int p = 0; p < 2; p++) {
                                int e = eh * 2 + p;
                                float bb = p ? bb1 : bb0;
                                float h0 = fmaxf(p0[j][e] + p1[j][e] + bb, 0.0f);
                                float h1 = fmaxf(p0[j][e] + p2[j][e] + bb, 0.0f);
                                hv[p] = fmaf(att[j][e], h0 - h1, h1);
                            }
                            int row = wm * 16 + g + eh * 8;
                            char* d = smem + SM_A + (colg >> 7) * TILE + swz(row, colg & 127);
                            *(__half2*)d = __floats2half2_rn(hv[0], hv[1]);
                        }
                    }
                }
            }
        } else {
            const int hu = h - 16, u = hu >> 1, part = hu & 1;
            const int nh = u / 5, kc = u % 5;
            if (kc == 0 && part == 0) {
                #pragma unroll
                for (int i = 0; i < 2; i++)
                    #pragma unroll
                    for (int j = 0; j < 4; j++)
                        #pragma unroll
                        for (int e = 0; e < 4; e++) xacc[i][j][e] = 0.0f;
            }
            wgemm_l3r(xacc, aL3 + (uint32_t)(kc * TILE), ax, aHi, bL3, bx, bHi, part * 4);
            if (kc == 4 && part == 1) {
                // L4: relu+b3, pack C-frags as A-frags, mma with register W4
                float b3v[4][2];
                #pragma unroll
                for (int j = 0; j < 4; j++) {
                    int c = nh * 128 + wn4 * 32 + j * 8 + 2 * tq;
                    b3v[j][0] = __ldg(&b3[c]);
                    b3v[j][1] = __ldg(&b3[c + 1]);
                }
                #pragma unroll
                for (int i = 0; i < 2; i++)
                    #pragma unroll
                    for (int kb4 = 0; kb4 < 2; kb4++) {
                        int j0 = kb4 * 2;
                        uint32_t af[4];
                        af[0] = packh2(fmaxf(xacc[i][j0][0]     + b3v[j0][0],     0.0f),
                                       fmaxf(xacc[i][j0][1]     + b3v[j0][1],     0.0f));
                        af[1] = packh2(fmaxf(xacc[i][j0][2]     + b3v[j0][0],     0.0f),
                                       fmaxf(xacc[i][j0][3]     + b3v[j0][1],     0.0f));
                        af[2] = packh2(fmaxf(xacc[i][j0 + 1][0] + b3v[j0 + 1][0], 0.0f),
                                       fmaxf(xacc[i][j0 + 1][1] + b3v[j0 + 1][1], 0.0f));
                        af[3] = packh2(fmaxf(xacc[i][j0 + 1][2] + b3v[j0 + 1][0], 0.0f),
                                       fmaxf(xacc[i][j0 + 1][3] + b3v[j0 + 1][1], 0.0f));
                        mma16816(oat[i], af, w4f[nh][kb4][0], w4f[nh][kb4][1]);
                    }
            }
        }
        __syncthreads();

        // fetch schedule: depth-2, with the L1->L3 boundary bubble at h=14/15
        if (h <= 13)                  fetch_half(sbW, h + 2, t);
        else if (h == 15)             { fetch_half(sbW, 16, t); fetch_half(sbW, 17, t); }
        else if (h >= 16 && h <= 33)  fetch_half(sbW, h + 2, t);
    }

    // ---- final: 4-way cross-wn4 reduction, bias, tanh, store ----
    float* red = (float*)(smem + SM_W);   // 6KB, W buffer free now
    if (wn4 > 0) {
        #pragma unroll
        for (int i = 0; i < 2; i++) {
            int r0 = wm2 * 32 + i * 16 + g;
            *(float2*)&red[((wn4 - 1) * 64 + r0) * 8 + 2 * tq] =
                make_float2(oat[i][0], oat[i][1]);
            *(float2*)&red[((wn4 - 1) * 64 + r0 + 8) * 8 + 2 * tq] =
                make_float2(oat[i][2], oat[i][3]);
        }
    }
    __syncthreads();
    if (wn4 == 0) {
        float bb0 = __ldg(&b4[2 * tq]), bb1 = __ldg(&b4[2 * tq + 1]);
        #pragma unroll
        for (int i = 0; i < 2; i++) {
            int r0 = wm2 * 32 + i * 16 + g;
            size_t gr = (size_t)cta * 64 + r0;
            float s00 = oat[i][0], s01 = oat[i][1], s10 = oat[i][2], s11 = oat[i][3];
            #pragma unroll
            for (int w = 0; w < 3; w++) {
                float2 v0 = *(float2*)&red[(w * 64 + r0) * 8 + 2 * tq];
                float2 v1 = *(float2*)&red[(w * 64 + r0 + 8) * 8 + 2 * tq];
                s00 += v0.x; s01 += v0.y; s10 += v1.x; s11 += v1.y;
            }
            *(float2*)&out[gr * 8 + 2 * tq] =
                make_float2(tanhf(s00 + bb0), tanhf(s01 + bb1));
            *(float2*)&out[(gr + 8) * 8 + 2 * tq] =
                make_float2(tanhf(s10 + bb0), tanhf(s11 + bb1));
        }
    }
}

// ---------------------------------------------------------------------------
// kernel_launch — 2 launches, graph-capturable, allocation-free.
// Inputs: state, W1, b1, W2, b2, W3, b3, W4, b4
// ---------------------------------------------------------------------------
extern "C" void kernel_launch(void* const* d_in, const int* in_sizes, int n_in,
                              void* d_out, int out_size)
{
    const float* state = (const float*)d_in[0];
    const float* W1    = (const float*)d_in[1];
    const float* b1    = (const float*)d_in[2];
    const float* W2    = (const float*)d_in[3];
    const float* b2    = (const float*)d_in[4];
    const float* W3    = (const float*)d_in[5];
    const float* b3    = (const float*)d_in[6];
    const float* W4    = (const float*)d_in[7];
    const float* b4    = (const float*)d_in[8];
    float* out = (float*)d_out;

    cudaFuncSetAttribute(actor_main,
                         cudaFuncAttributeMaxDynamicSharedMemorySize, SMEM_BYTES);

    convert_weights<<<18, 256>>>(W1, W2, W3);
    actor_main<<<NCTA, 256, SMEM_BYTES>>>(state, b1, b2, b3, W4, b4, out);
}